// round 1
// baseline (speedup 1.0000x reference)
#include <cuda_runtime.h>
#include <math.h>

// Causal flash attention: B=32, T=2048, D=64, fp32.
// One CTA per (batch, 64-query tile). 256 threads, each owns a 4x4 tile of the
// 64x64 score matrix and a 4x4 tile of the 64-dim output accumulator.
// Q,K stored transposed + xor-swizzled in smem for conflict-free LDS.128.
// P@V uses width-16 warp shuffles to broadcast P rows (no P smem buffer).

#define BATCH 32
#define SEQ   2048
#define HD    64

__global__ __launch_bounds__(256, 2)
void fa64_kernel(const float* __restrict__ Q, const float* __restrict__ K,
                 const float* __restrict__ V, float* __restrict__ O) {
    __shared__ float Qt[64 * 64];   // Qt[d*64 + (r ^ (d & 28))] = Q[r][d]
    __shared__ float Kt[64 * 64];   // same layout for K
    __shared__ float Vs[64 * 64];   // row-major V tile

    const int b   = blockIdx.y;
    const int qt  = (int)gridDim.x - 1 - (int)blockIdx.x;  // biggest tiles first
    const int tid = threadIdx.x;
    const int ty  = tid >> 4;   // 0..15 -> query rows ty*4..+3
    const int tx  = tid & 15;   // 0..15 -> key cols / dim cols tx*4..+3

    // fold 1/sqrt(64) and log2(e) so we can use exp2f
    const float sc = 0.125f * 1.44269504088896340736f;

    const size_t baseQ = ((size_t)b * SEQ + (size_t)qt * 64) * HD;

    // ---- load Q tile, transposed + swizzled ----
    {
        const float4* g = reinterpret_cast<const float4*>(Q + baseQ);
        #pragma unroll
        for (int it = 0; it < 4; ++it) {
            int idx = it * 256 + tid;
            int r   = idx >> 4;       // query row within tile
            int c4  = idx & 15;       // float4 index along dim
            float4 v = g[r * 16 + c4];
            int d0 = c4 * 4;
            Qt[(d0 + 0) * 64 + (r ^ ((d0 + 0) & 28))] = v.x;
            Qt[(d0 + 1) * 64 + (r ^ ((d0 + 1) & 28))] = v.y;
            Qt[(d0 + 2) * 64 + (r ^ ((d0 + 2) & 28))] = v.z;
            Qt[(d0 + 3) * 64 + (r ^ ((d0 + 3) & 28))] = v.w;
        }
    }

    float m_i[4], l_i[4], o[4][4];
    #pragma unroll
    for (int i = 0; i < 4; ++i) {
        m_i[i] = -INFINITY;
        l_i[i] = 0.0f;
        #pragma unroll
        for (int j = 0; j < 4; ++j) o[i][j] = 0.0f;
    }

    for (int jt = 0; jt <= qt; ++jt) {
        __syncthreads();  // previous tile fully consumed

        // ---- load K (transposed+swizzled) and V (row-major) tiles ----
        const float4* gk = reinterpret_cast<const float4*>(
            K + ((size_t)b * SEQ + (size_t)jt * 64) * HD);
        const float4* gv = reinterpret_cast<const float4*>(
            V + ((size_t)b * SEQ + (size_t)jt * 64) * HD);
        #pragma unroll
        for (int it = 0; it < 4; ++it) {
            int idx = it * 256 + tid;
            int r   = idx >> 4;
            int c4  = idx & 15;
            float4 kv = gk[r * 16 + c4];
            int d0 = c4 * 4;
            Kt[(d0 + 0) * 64 + (r ^ ((d0 + 0) & 28))] = kv.x;
            Kt[(d0 + 1) * 64 + (r ^ ((d0 + 1) & 28))] = kv.y;
            Kt[(d0 + 2) * 64 + (r ^ ((d0 + 2) & 28))] = kv.z;
            Kt[(d0 + 3) * 64 + (r ^ ((d0 + 3) & 28))] = kv.w;
            reinterpret_cast<float4*>(Vs)[r * 16 + c4] = gv[r * 16 + c4];
        }
        __syncthreads();

        // ---- S = Q K^T (4x4 per thread) ----
        float acc[4][4];
        #pragma unroll
        for (int i = 0; i < 4; ++i)
            #pragma unroll
            for (int j = 0; j < 4; ++j) acc[i][j] = 0.0f;

        #pragma unroll 8
        for (int k = 0; k < 64; ++k) {
            const int f = k & 28;
            float4 q = *reinterpret_cast<const float4*>(&Qt[k * 64 + ((ty * 4) ^ f)]);
            float4 kk = *reinterpret_cast<const float4*>(&Kt[k * 64 + ((tx * 4) ^ f)]);
            acc[0][0] += q.x * kk.x; acc[0][1] += q.x * kk.y; acc[0][2] += q.x * kk.z; acc[0][3] += q.x * kk.w;
            acc[1][0] += q.y * kk.x; acc[1][1] += q.y * kk.y; acc[1][2] += q.y * kk.z; acc[1][3] += q.y * kk.w;
            acc[2][0] += q.z * kk.x; acc[2][1] += q.z * kk.y; acc[2][2] += q.z * kk.z; acc[2][3] += q.z * kk.w;
            acc[3][0] += q.w * kk.x; acc[3][1] += q.w * kk.y; acc[3][2] += q.w * kk.z; acc[3][3] += q.w * kk.w;
        }

        // ---- online softmax (rows spread over tx: width-16 shfl reductions) ----
        const bool diag = (jt == qt);
        float p[4][4];
        #pragma unroll
        for (int i = 0; i < 4; ++i) {
            #pragma unroll
            for (int j = 0; j < 4; ++j) {
                float s = acc[i][j] * sc;
                if (diag && (tx * 4 + j > ty * 4 + i)) s = -INFINITY;
                acc[i][j] = s;
            }
            float mx = fmaxf(fmaxf(acc[i][0], acc[i][1]), fmaxf(acc[i][2], acc[i][3]));
            mx = fmaxf(mx, __shfl_xor_sync(0xffffffffu, mx, 1, 16));
            mx = fmaxf(mx, __shfl_xor_sync(0xffffffffu, mx, 2, 16));
            mx = fmaxf(mx, __shfl_xor_sync(0xffffffffu, mx, 4, 16));
            mx = fmaxf(mx, __shfl_xor_sync(0xffffffffu, mx, 8, 16));
            const float mn = fmaxf(m_i[i], mx);
            const float al = exp2f(m_i[i] - mn);  // m_i=-inf first tile -> 0

            float s0 = 0.0f;
            #pragma unroll
            for (int j = 0; j < 4; ++j) {
                p[i][j] = exp2f(acc[i][j] - mn);
                s0 += p[i][j];
            }
            s0 += __shfl_xor_sync(0xffffffffu, s0, 1, 16);
            s0 += __shfl_xor_sync(0xffffffffu, s0, 2, 16);
            s0 += __shfl_xor_sync(0xffffffffu, s0, 4, 16);
            s0 += __shfl_xor_sync(0xffffffffu, s0, 8, 16);

            l_i[i] = l_i[i] * al + s0;
            m_i[i] = mn;
            #pragma unroll
            for (int j = 0; j < 4; ++j) o[i][j] *= al;
        }

        // ---- O += P @ V : broadcast P columns via width-16 shuffles ----
        #pragma unroll 2
        for (int so = 0; so < 16; ++so) {
            #pragma unroll
            for (int jj = 0; jj < 4; ++jj) {
                const float b0 = __shfl_sync(0xffffffffu, p[0][jj], so, 16);
                const float b1 = __shfl_sync(0xffffffffu, p[1][jj], so, 16);
                const float b2 = __shfl_sync(0xffffffffu, p[2][jj], so, 16);
                const float b3 = __shfl_sync(0xffffffffu, p[3][jj], so, 16);
                const float4 v =
                    *reinterpret_cast<const float4*>(&Vs[(so * 4 + jj) * 64 + tx * 4]);
                o[0][0] += b0 * v.x; o[0][1] += b0 * v.y; o[0][2] += b0 * v.z; o[0][3] += b0 * v.w;
                o[1][0] += b1 * v.x; o[1][1] += b1 * v.y; o[1][2] += b1 * v.z; o[1][3] += b1 * v.w;
                o[2][0] += b2 * v.x; o[2][1] += b2 * v.y; o[2][2] += b2 * v.z; o[2][3] += b2 * v.w;
                o[3][0] += b3 * v.x; o[3][1] += b3 * v.y; o[3][2] += b3 * v.z; o[3][3] += b3 * v.w;
            }
        }
    }

    // ---- normalize and store ----
    float* Ob = O + baseQ;
    #pragma unroll
    for (int i = 0; i < 4; ++i) {
        const float inv = 1.0f / l_i[i];
        float4 r;
        r.x = o[i][0] * inv;
        r.y = o[i][1] * inv;
        r.z = o[i][2] * inv;
        r.w = o[i][3] * inv;
        reinterpret_cast<float4*>(Ob + (size_t)(ty * 4 + i) * HD)[tx] = r;
    }
}

extern "C" void kernel_launch(void* const* d_in, const int* in_sizes, int n_in,
                              void* d_out, int out_size) {
    const float* Q = (const float*)d_in[0];
    const float* K = (const float*)d_in[1];
    const float* V = (const float*)d_in[2];
    float* O = (float*)d_out;

    dim3 grid(SEQ / 64, BATCH);  // 32 x 32
    fa64_kernel<<<grid, 256>>>(Q, K, V, O);
}

// round 2
// speedup vs baseline: 3.1429x; 3.1429x over previous
#include <cuda_runtime.h>
#include <math.h>

// Causal flash attention, B=32, T=2048, D=64, fp32 I/O.
// tf32 mma.sync (m16n8k8) for both GEMMs, fp32 accumulation.
// 128 threads (4 warps) per CTA; each warp owns 16 query rows x full 64-key tile.
// K/V tf32-rounded at smem store; xor swizzles give conflict-free B-frag loads.
// P is permuted C-frag -> A-frag with quad shuffles (no P smem buffer).

#define BATCH 32
#define SEQ   2048
#define HD    64

__device__ __forceinline__ unsigned f2tf(float f) {
    unsigned u;
    asm("cvt.rna.tf32.f32 %0, %1;" : "=r"(u) : "f"(f));
    return u;
}

__device__ __forceinline__ void mma_tf32(float* c, const unsigned* a, unsigned b0, unsigned b1) {
    asm volatile(
        "mma.sync.aligned.m16n8k8.row.col.f32.tf32.tf32.f32 "
        "{%0,%1,%2,%3}, {%4,%5,%6,%7}, {%8,%9}, {%0,%1,%2,%3};\n"
        : "+f"(c[0]), "+f"(c[1]), "+f"(c[2]), "+f"(c[3])
        : "r"(a[0]), "r"(a[1]), "r"(a[2]), "r"(a[3]), "r"(b0), "r"(b1));
}

__global__ __launch_bounds__(128)
void fa_mma_kernel(const float* __restrict__ Q, const float* __restrict__ K,
                   const float* __restrict__ V, float* __restrict__ O) {
    __shared__ float Ks[64 * 64];
    __shared__ float Vs[64 * 64];

    const int b    = blockIdx.y;
    const int qt   = (int)gridDim.x - 1 - (int)blockIdx.x;  // big tiles first
    const int tid  = threadIdx.x;
    const int warp = tid >> 5;
    const int lane = tid & 31;
    const int g    = lane >> 2;   // 0..7
    const int q4   = lane & 3;    // 0..3
    const int r0   = warp * 16;   // this warp's query-row base within tile

    const unsigned FULL = 0xffffffffu;
    const float sc = 0.125f * 1.44269504088896340736f;  // 1/sqrt(64) * log2(e)
    const size_t baseQ = ((size_t)b * SEQ + (size_t)qt * 64) * HD;

    // ---- stage Q row-major into Ks, then pull A-fragments (once per CTA) ----
    {
        const float4* gq = reinterpret_cast<const float4*>(Q + baseQ);
        #pragma unroll
        for (int it = 0; it < 8; ++it)
            reinterpret_cast<float4*>(Ks)[it * 128 + tid] = gq[it * 128 + tid];
    }
    __syncthreads();

    unsigned aQ[8][4];
    #pragma unroll
    for (int j = 0; j < 8; ++j) {
        aQ[j][0] = f2tf(Ks[(r0 + g    ) * 64 + 8 * j + q4    ] * sc);
        aQ[j][1] = f2tf(Ks[(r0 + g + 8) * 64 + 8 * j + q4    ] * sc);
        aQ[j][2] = f2tf(Ks[(r0 + g    ) * 64 + 8 * j + q4 + 4] * sc);
        aQ[j][3] = f2tf(Ks[(r0 + g + 8) * 64 + 8 * j + q4 + 4] * sc);
    }

    float m_[2] = {-INFINITY, -INFINITY};
    float l_[2] = {0.f, 0.f};
    float o[8][4];
    #pragma unroll
    for (int n = 0; n < 8; ++n)
        #pragma unroll
        for (int k = 0; k < 4; ++k) o[n][k] = 0.f;

    for (int jt = 0; jt <= qt; ++jt) {
        __syncthreads();  // previous tile fully consumed

        // ---- load K/V tiles: tf32-round once, swizzled stores ----
        const float4* gk = reinterpret_cast<const float4*>(
            K + ((size_t)b * SEQ + (size_t)jt * 64) * HD);
        const float4* gv = reinterpret_cast<const float4*>(
            V + ((size_t)b * SEQ + (size_t)jt * 64) * HD);
        #pragma unroll
        for (int it = 0; it < 8; ++it) {
            int idx = it * 128 + tid;
            int r = idx >> 4, c4 = idx & 15;
            float4 kk = gk[idx];
            kk.x = __uint_as_float(f2tf(kk.x));
            kk.y = __uint_as_float(f2tf(kk.y));
            kk.z = __uint_as_float(f2tf(kk.z));
            kk.w = __uint_as_float(f2tf(kk.w));
            int pk = (c4 * 4) ^ ((r & 7) << 2);
            *reinterpret_cast<float4*>(&Ks[r * 64 + pk]) = kk;
            float4 vv = gv[idx];
            vv.x = __uint_as_float(f2tf(vv.x));
            vv.y = __uint_as_float(f2tf(vv.y));
            vv.z = __uint_as_float(f2tf(vv.z));
            vv.w = __uint_as_float(f2tf(vv.w));
            int pv = (c4 * 4) ^ ((r & 3) << 3);
            *reinterpret_cast<float4*>(&Vs[r * 64 + pv]) = vv;
        }
        __syncthreads();

        const bool diag = (jt == qt);
        const int nmax = diag ? (2 * warp + 2) : 8;  // causal tile-skip bound

        // ---- S = Q K^T ----
        float s[8][4];
        #pragma unroll
        for (int n = 0; n < 8; ++n)
            #pragma unroll
            for (int k = 0; k < 4; ++k) s[n][k] = 0.f;

        #pragma unroll
        for (int j = 0; j < 8; ++j) {
            #pragma unroll
            for (int n = 0; n < 8; ++n) {
                if (n < nmax) {
                    const int row = n * 8 + g;
                    const int sw  = g << 2;
                    unsigned b0 = __float_as_uint(Ks[row * 64 + ((8 * j + q4    ) ^ sw)]);
                    unsigned b1 = __float_as_uint(Ks[row * 64 + ((8 * j + q4 + 4) ^ sw)]);
                    mma_tf32(s[n], aQ[j], b0, b1);
                }
            }
        }

        // ---- causal mask (diag tile) ----
        if (diag) {
            #pragma unroll
            for (int n = 0; n < 8; ++n) {
                const int c0 = n * 8 + 2 * q4;
                if (c0     > r0 + g    ) s[n][0] = -INFINITY;
                if (c0 + 1 > r0 + g    ) s[n][1] = -INFINITY;
                if (c0     > r0 + g + 8) s[n][2] = -INFINITY;
                if (c0 + 1 > r0 + g + 8) s[n][3] = -INFINITY;
            }
        }

        // ---- online softmax (rows g and g+8; quad reductions) ----
        float mx0 = -INFINITY, mx1 = -INFINITY;
        #pragma unroll
        for (int n = 0; n < 8; ++n) {
            mx0 = fmaxf(mx0, fmaxf(s[n][0], s[n][1]));
            mx1 = fmaxf(mx1, fmaxf(s[n][2], s[n][3]));
        }
        mx0 = fmaxf(mx0, __shfl_xor_sync(FULL, mx0, 1));
        mx0 = fmaxf(mx0, __shfl_xor_sync(FULL, mx0, 2));
        mx1 = fmaxf(mx1, __shfl_xor_sync(FULL, mx1, 1));
        mx1 = fmaxf(mx1, __shfl_xor_sync(FULL, mx1, 2));

        const float mn0 = fmaxf(m_[0], mx0);
        const float mn1 = fmaxf(m_[1], mx1);
        const float al0 = exp2f(m_[0] - mn0);
        const float al1 = exp2f(m_[1] - mn1);

        float sm0 = 0.f, sm1 = 0.f;
        #pragma unroll
        for (int n = 0; n < 8; ++n) {
            s[n][0] = exp2f(s[n][0] - mn0); sm0 += s[n][0];
            s[n][1] = exp2f(s[n][1] - mn0); sm0 += s[n][1];
            s[n][2] = exp2f(s[n][2] - mn1); sm1 += s[n][2];
            s[n][3] = exp2f(s[n][3] - mn1); sm1 += s[n][3];
        }
        sm0 += __shfl_xor_sync(FULL, sm0, 1);
        sm0 += __shfl_xor_sync(FULL, sm0, 2);
        sm1 += __shfl_xor_sync(FULL, sm1, 1);
        sm1 += __shfl_xor_sync(FULL, sm1, 2);

        l_[0] = l_[0] * al0 + sm0;  m_[0] = mn0;
        l_[1] = l_[1] * al1 + sm1;  m_[1] = mn1;
        #pragma unroll
        for (int n = 0; n < 8; ++n) {
            o[n][0] *= al0; o[n][1] *= al0;
            o[n][2] *= al1; o[n][3] *= al1;
        }

        // ---- O += P @ V : C-frag -> A-frag via quad shuffles ----
        #pragma unroll
        for (int j = 0; j < 8; ++j) {
            if (j < nmax) {  // diag: chunks fully above diagonal contribute p==0
                const int srcA = (lane & 28) | (q4 >> 1);
                const int srcC = srcA + 2;
                float y0 = __shfl_sync(FULL, s[j][0], srcA);
                float y1 = __shfl_sync(FULL, s[j][1], srcA);
                float y2 = __shfl_sync(FULL, s[j][2], srcA);
                float y3 = __shfl_sync(FULL, s[j][3], srcA);
                float z0 = __shfl_sync(FULL, s[j][0], srcC);
                float z1 = __shfl_sync(FULL, s[j][1], srcC);
                float z2 = __shfl_sync(FULL, s[j][2], srcC);
                float z3 = __shfl_sync(FULL, s[j][3], srcC);
                unsigned a[4];
                const bool odd = (q4 & 1);
                a[0] = f2tf(odd ? y1 : y0);
                a[1] = f2tf(odd ? y3 : y2);
                a[2] = f2tf(odd ? z1 : z0);
                a[3] = f2tf(odd ? z3 : z2);
                #pragma unroll
                for (int n = 0; n < 8; ++n) {
                    const int rs = 8 * j + q4;
                    const int sw = q4 << 3;
                    unsigned b0 = __float_as_uint(Vs[ rs      * 64 + ((n * 8 + g) ^ sw)]);
                    unsigned b1 = __float_as_uint(Vs[(rs + 4) * 64 + ((n * 8 + g) ^ sw)]);
                    mma_tf32(o[n], a, b0, b1);
                }
            }
        }
    }

    // ---- normalize and store ----
    float* Ob = O + baseQ;
    const float inv0 = 1.f / l_[0];
    const float inv1 = 1.f / l_[1];
    #pragma unroll
    for (int n = 0; n < 8; ++n) {
        float2 w0 = make_float2(o[n][0] * inv0, o[n][1] * inv0);
        float2 w1 = make_float2(o[n][2] * inv1, o[n][3] * inv1);
        *reinterpret_cast<float2*>(Ob + (size_t)(r0 + g    ) * HD + n * 8 + 2 * q4) = w0;
        *reinterpret_cast<float2*>(Ob + (size_t)(r0 + g + 8) * HD + n * 8 + 2 * q4) = w1;
    }
}

extern "C" void kernel_launch(void* const* d_in, const int* in_sizes, int n_in,
                              void* d_out, int out_size) {
    const float* Q = (const float*)d_in[0];
    const float* K = (const float*)d_in[1];
    const float* V = (const float*)d_in[2];
    float* O = (float*)d_out;

    dim3 grid(SEQ / 64, BATCH);  // 32 x 32
    fa_mma_kernel<<<grid, 128>>>(Q, K, V, O);
}

// round 3
// speedup vs baseline: 4.0372x; 1.2845x over previous
#include <cuda_runtime.h>
#include <math.h>

// Causal flash attention, B=32, T=2048, D=64, fp32 I/O.
// QK^T: tf32 mma m16n8k8 (K pair-interleaved in smem -> LDS.64 B-frags).
// P@V : fp16 mma m16n8k16 (P packed straight from C-frags, V via ldmatrix.trans).
// fp32 accumulation everywhere; softmax in fp32 with ex2.approx.

#define BATCH 32
#define SEQ   2048
#define HD    64

__device__ __forceinline__ unsigned f2tf(float f) {
    unsigned u;
    asm("cvt.rna.tf32.f32 %0, %1;" : "=r"(u) : "f"(f));
    return u;
}

__device__ __forceinline__ float ex2(float x) {
    float y;
    asm("ex2.approx.f32 %0, %1;" : "=f"(y) : "f"(x));
    return y;
}

__device__ __forceinline__ unsigned packh2(float hi, float lo) {
    unsigned d;
    asm("cvt.rn.f16x2.f32 %0, %1, %2;" : "=r"(d) : "f"(hi), "f"(lo));
    return d;
}

__device__ __forceinline__ void mma_tf32(float* c, const unsigned* a, unsigned b0, unsigned b1) {
    asm volatile(
        "mma.sync.aligned.m16n8k8.row.col.f32.tf32.tf32.f32 "
        "{%0,%1,%2,%3}, {%4,%5,%6,%7}, {%8,%9}, {%0,%1,%2,%3};\n"
        : "+f"(c[0]), "+f"(c[1]), "+f"(c[2]), "+f"(c[3])
        : "r"(a[0]), "r"(a[1]), "r"(a[2]), "r"(a[3]), "r"(b0), "r"(b1));
}

__device__ __forceinline__ void mma_f16(float* c, const unsigned* a, unsigned b0, unsigned b1) {
    asm volatile(
        "mma.sync.aligned.m16n8k16.row.col.f32.f16.f16.f32 "
        "{%0,%1,%2,%3}, {%4,%5,%6,%7}, {%8,%9}, {%0,%1,%2,%3};\n"
        : "+f"(c[0]), "+f"(c[1]), "+f"(c[2]), "+f"(c[3])
        : "r"(a[0]), "r"(a[1]), "r"(a[2]), "r"(a[3]), "r"(b0), "r"(b1));
}

__global__ __launch_bounds__(128)
void fa_mma_kernel(const float* __restrict__ Q, const float* __restrict__ K,
                   const float* __restrict__ V, float* __restrict__ O) {
    __shared__ float Ks[64 * 64];                       // K tf32, pair-interleaved+swizzled
    __shared__ __align__(16) unsigned Vh[64 * 32];      // V fp16, 16B-chunk swizzled

    const int b    = blockIdx.y;
    const int qt   = (int)gridDim.x - 1 - (int)blockIdx.x;  // big tiles first
    const int tid  = threadIdx.x;
    const int warp = tid >> 5;
    const int lane = tid & 31;
    const int g    = lane >> 2;   // 0..7
    const int q4   = lane & 3;    // 0..3
    const int r0   = warp * 16;

    const unsigned FULL = 0xffffffffu;
    const float sc = 0.125f * 1.44269504088896340736f;
    const size_t baseQ = ((size_t)b * SEQ + (size_t)qt * 64) * HD;

    // per-thread ldmatrix source coords (x4: 4 matrices of 8 rows)
    const int lm_m   = lane >> 3;          // matrix id 0..3
    const int lm_r   = lane & 7;           // row within matrix
    const int lm_sr0 = 8 * (lm_m & 1) + lm_r;   // s-row offset within 16-row k-chunk
    const int lm_ch0 = lm_m >> 1;               // n-chunk offset within pair
    const unsigned vh_base = (unsigned)__cvta_generic_to_shared(Vh);

    // ---- stage Q row-major into Ks, pull A-fragments once ----
    {
        const float4* gq = reinterpret_cast<const float4*>(Q + baseQ);
        #pragma unroll
        for (int it = 0; it < 8; ++it)
            reinterpret_cast<float4*>(Ks)[it * 128 + tid] = gq[it * 128 + tid];
    }
    __syncthreads();

    unsigned aQ[8][4];
    #pragma unroll
    for (int j = 0; j < 8; ++j) {
        aQ[j][0] = f2tf(Ks[(r0 + g    ) * 64 + 8 * j + q4    ] * sc);
        aQ[j][1] = f2tf(Ks[(r0 + g + 8) * 64 + 8 * j + q4    ] * sc);
        aQ[j][2] = f2tf(Ks[(r0 + g    ) * 64 + 8 * j + q4 + 4] * sc);
        aQ[j][3] = f2tf(Ks[(r0 + g + 8) * 64 + 8 * j + q4 + 4] * sc);
    }

    float m_[2] = {-INFINITY, -INFINITY};
    float l_[2] = {0.f, 0.f};
    float o[8][4];
    #pragma unroll
    for (int n = 0; n < 8; ++n)
        #pragma unroll
        for (int k = 0; k < 4; ++k) o[n][k] = 0.f;

    for (int jt = 0; jt <= qt; ++jt) {
        __syncthreads();  // previous tile fully consumed

        // ---- K tile: tf32 + pair-interleave (k, k+4 adjacent) + swizzle ----
        {
            const float4* gk = reinterpret_cast<const float4*>(
                K + ((size_t)b * SEQ + (size_t)jt * 64) * HD);
            #pragma unroll
            for (int it = 0; it < 4; ++it) {
                int idx = it * 128 + tid;
                int r = idx >> 3, j = idx & 7;     // row, 8-col chunk
                float4 v0 = gk[r * 16 + 2 * j];
                float4 v1 = gk[r * 16 + 2 * j + 1];
                float4 o0, o1;
                o0.x = __uint_as_float(f2tf(v0.x)); o0.y = __uint_as_float(f2tf(v1.x));
                o0.z = __uint_as_float(f2tf(v0.y)); o0.w = __uint_as_float(f2tf(v1.y));
                o1.x = __uint_as_float(f2tf(v0.z)); o1.y = __uint_as_float(f2tf(v1.z));
                o1.z = __uint_as_float(f2tf(v0.w)); o1.w = __uint_as_float(f2tf(v1.w));
                int base = r * 64 + 2 * ((4 * j) ^ ((r & 7) << 2));
                *reinterpret_cast<float4*>(&Ks[base    ]) = o0;
                *reinterpret_cast<float4*>(&Ks[base + 4]) = o1;
            }
        }
        // ---- V tile: fp16, 16B-chunk swizzle ----
        {
            const float4* gv = reinterpret_cast<const float4*>(
                V + ((size_t)b * SEQ + (size_t)jt * 64) * HD);
            #pragma unroll
            for (int it = 0; it < 8; ++it) {
                int idx = it * 128 + tid;
                int s = idx >> 4, c4 = idx & 15;
                float4 f = gv[idx];
                unsigned u0 = packh2(f.y, f.x);
                unsigned u1 = packh2(f.w, f.z);
                int cc = c4 >> 1, half = c4 & 1;
                unsigned off = (unsigned)(s * 128 + (((cc) ^ (s & 7)) << 4) + (half << 3));
                *reinterpret_cast<uint2*>(reinterpret_cast<char*>(Vh) + off) =
                    make_uint2(u0, u1);
            }
        }
        __syncthreads();

        const bool diag = (jt == qt);
        const int nmax = diag ? (2 * warp + 2) : 8;
        const int kcmax = diag ? (warp + 1) : 4;

        // ---- S = Q K^T : one LDS.64 per mma ----
        float s[8][4];
        #pragma unroll
        for (int n = 0; n < 8; ++n)
            #pragma unroll
            for (int k = 0; k < 4; ++k) s[n][k] = 0.f;

        #pragma unroll
        for (int j = 0; j < 8; ++j) {
            #pragma unroll
            for (int n = 0; n < 8; ++n) {
                if (n < nmax) {
                    const float2 kk = *reinterpret_cast<const float2*>(
                        &Ks[(n * 8 + g) * 64 + 2 * ((4 * j + q4) ^ (g << 2))]);
                    mma_tf32(s[n], aQ[j], __float_as_uint(kk.x), __float_as_uint(kk.y));
                }
            }
        }

        // ---- causal mask (diag tile) ----
        if (diag) {
            #pragma unroll
            for (int n = 0; n < 8; ++n) {
                const int c0 = n * 8 + 2 * q4;
                if (c0     > r0 + g    ) s[n][0] = -INFINITY;
                if (c0 + 1 > r0 + g    ) s[n][1] = -INFINITY;
                if (c0     > r0 + g + 8) s[n][2] = -INFINITY;
                if (c0 + 1 > r0 + g + 8) s[n][3] = -INFINITY;
            }
        }

        // ---- online softmax ----
        float mx0 = -INFINITY, mx1 = -INFINITY;
        #pragma unroll
        for (int n = 0; n < 8; ++n) {
            mx0 = fmaxf(mx0, fmaxf(s[n][0], s[n][1]));
            mx1 = fmaxf(mx1, fmaxf(s[n][2], s[n][3]));
        }
        mx0 = fmaxf(mx0, __shfl_xor_sync(FULL, mx0, 1));
        mx0 = fmaxf(mx0, __shfl_xor_sync(FULL, mx0, 2));
        mx1 = fmaxf(mx1, __shfl_xor_sync(FULL, mx1, 1));
        mx1 = fmaxf(mx1, __shfl_xor_sync(FULL, mx1, 2));

        const float mn0 = fmaxf(m_[0], mx0);
        const float mn1 = fmaxf(m_[1], mx1);
        const float al0 = ex2(m_[0] - mn0);
        const float al1 = ex2(m_[1] - mn1);

        float sm0 = 0.f, sm1 = 0.f;
        #pragma unroll
        for (int n = 0; n < 8; ++n) {
            s[n][0] = ex2(s[n][0] - mn0); sm0 += s[n][0];
            s[n][1] = ex2(s[n][1] - mn0); sm0 += s[n][1];
            s[n][2] = ex2(s[n][2] - mn1); sm1 += s[n][2];
            s[n][3] = ex2(s[n][3] - mn1); sm1 += s[n][3];
        }
        sm0 += __shfl_xor_sync(FULL, sm0, 1);
        sm0 += __shfl_xor_sync(FULL, sm0, 2);
        sm1 += __shfl_xor_sync(FULL, sm1, 1);
        sm1 += __shfl_xor_sync(FULL, sm1, 2);

        l_[0] = l_[0] * al0 + sm0;  m_[0] = mn0;
        l_[1] = l_[1] * al1 + sm1;  m_[1] = mn1;
        #pragma unroll
        for (int n = 0; n < 8; ++n) {
            o[n][0] *= al0; o[n][1] *= al0;
            o[n][2] *= al1; o[n][3] *= al1;
        }

        // ---- P -> fp16 A-frags (C-frag layout matches A-frag: no shuffles) ----
        unsigned pa[4][4];
        #pragma unroll
        for (int kc = 0; kc < 4; ++kc) {
            if (kc < kcmax) {
                pa[kc][0] = packh2(s[2 * kc    ][1], s[2 * kc    ][0]);
                pa[kc][1] = packh2(s[2 * kc    ][3], s[2 * kc    ][2]);
                pa[kc][2] = packh2(s[2 * kc + 1][1], s[2 * kc + 1][0]);
                pa[kc][3] = packh2(s[2 * kc + 1][3], s[2 * kc + 1][2]);
            }
        }

        // ---- O += P @ V : ldmatrix.x4.trans B-frags, fp16 mma ----
        #pragma unroll
        for (int np = 0; np < 4; ++np) {
            #pragma unroll
            for (int kc = 0; kc < 4; ++kc) {
                if (kc < kcmax) {
                    const int s_row = 16 * kc + lm_sr0;
                    const unsigned addr = vh_base + (unsigned)(
                        s_row * 128 + (((2 * np + lm_ch0) ^ (s_row & 7)) << 4));
                    unsigned b0, b1, b2, b3;
                    asm volatile(
                        "ldmatrix.sync.aligned.m8n8.x4.trans.shared.b16 "
                        "{%0,%1,%2,%3}, [%4];"
                        : "=r"(b0), "=r"(b1), "=r"(b2), "=r"(b3) : "r"(addr));
                    mma_f16(o[2 * np    ], pa[kc], b0, b1);
                    mma_f16(o[2 * np + 1], pa[kc], b2, b3);
                }
            }
        }
    }

    // ---- normalize and store ----
    float* Ob = O + baseQ;
    const float inv0 = 1.f / l_[0];
    const float inv1 = 1.f / l_[1];
    #pragma unroll
    for (int n = 0; n < 8; ++n) {
        float2 w0 = make_float2(o[n][0] * inv0, o[n][1] * inv0);
        float2 w1 = make_float2(o[n][2] * inv1, o[n][3] * inv1);
        *reinterpret_cast<float2*>(Ob + (size_t)(r0 + g    ) * HD + n * 8 + 2 * q4) = w0;
        *reinterpret_cast<float2*>(Ob + (size_t)(r0 + g + 8) * HD + n * 8 + 2 * q4) = w1;
    }
}

extern "C" void kernel_launch(void* const* d_in, const int* in_sizes, int n_in,
                              void* d_out, int out_size) {
    const float* Q = (const float*)d_in[0];
    const float* K = (const float*)d_in[1];
    const float* V = (const float*)d_in[2];
    float* O = (float*)d_out;

    dim3 grid(SEQ / 64, BATCH);  // 32 x 32
    fa_mma_kernel<<<grid, 128>>>(Q, K, V, O);
}